// round 1
// baseline (speedup 1.0000x reference)
#include <cuda_runtime.h>
#include <math_constants.h>

#define B_  32
#define TQ  512
#define TK  2048
#define DD  512

// Scores / probabilities scratch: 32*512*2048 floats = 128 MiB (static device global; no runtime alloc)
__device__ float g_scores[(size_t)B_ * TQ * TK];

#define BM 128
#define BN 128
#define BK 16
#define TM 8
#define TN 8
// 256 threads = 16x16 thread grid, each computes an 8x8 micro-tile

// ---------------------------------------------------------------------------
// GEMM 1 (NT): S[b] = Q[b] @ K[b]^T
//   Q: [TQ, DD] row-major, K(enc): [TK, DD] row-major, S: [TQ, TK] row-major
// ---------------------------------------------------------------------------
__global__ __launch_bounds__(256) void gemm_qk(const float* __restrict__ Q,
                                               const float* __restrict__ Kv) {
    int b = blockIdx.z;
    const float* A  = Q  + (size_t)b * TQ * DD;
    const float* Bm = Kv + (size_t)b * TK * DD;
    float*       C  = g_scores + (size_t)b * TQ * TK;

    int bm = blockIdx.y * BM;
    int bn = blockIdx.x * BN;

    __shared__ float As[BK][BM];
    __shared__ float Bs[BK][BN];

    float acc[TM][TN] = {};
    int tid = threadIdx.x;
    int tx = tid & 15, ty = tid >> 4;

    for (int k0 = 0; k0 < DD; k0 += BK) {
        // Load 128x16 A tile and 128x16 B tile (both K-contiguous), transpose into smem
        #pragma unroll
        for (int t = 0; t < 2; t++) {
            int j   = tid + t * 256;   // 0..511
            int row = j >> 2;          // 0..127
            int c4  = j & 3;           // 0..3 (group of 4 k's)
            float4 v = *(const float4*)&A [(size_t)(bm + row) * DD + k0 + c4 * 4];
            As[c4*4+0][row] = v.x; As[c4*4+1][row] = v.y;
            As[c4*4+2][row] = v.z; As[c4*4+3][row] = v.w;
            float4 w = *(const float4*)&Bm[(size_t)(bn + row) * DD + k0 + c4 * 4];
            Bs[c4*4+0][row] = w.x; Bs[c4*4+1][row] = w.y;
            Bs[c4*4+2][row] = w.z; Bs[c4*4+3][row] = w.w;
        }
        __syncthreads();

        #pragma unroll
        for (int kk = 0; kk < BK; kk++) {
            float4 a0 = *(const float4*)&As[kk][ty * TM];
            float4 a1 = *(const float4*)&As[kk][ty * TM + 4];
            float4 b0 = *(const float4*)&Bs[kk][tx * TN];
            float4 b1 = *(const float4*)&Bs[kk][tx * TN + 4];
            float ar[8] = {a0.x,a0.y,a0.z,a0.w,a1.x,a1.y,a1.z,a1.w};
            float br[8] = {b0.x,b0.y,b0.z,b0.w,b1.x,b1.y,b1.z,b1.w};
            #pragma unroll
            for (int i = 0; i < 8; i++)
                #pragma unroll
                for (int j = 0; j < 8; j++)
                    acc[i][j] = fmaf(ar[i], br[j], acc[i][j]);
        }
        __syncthreads();
    }

    #pragma unroll
    for (int i = 0; i < 8; i++) {
        int m = bm + ty * TM + i;
        float4* crow = (float4*)&C[(size_t)m * TK + bn + tx * TN];
        crow[0] = make_float4(acc[i][0], acc[i][1], acc[i][2], acc[i][3]);
        crow[1] = make_float4(acc[i][4], acc[i][5], acc[i][6], acc[i][7]);
    }
}

// ---------------------------------------------------------------------------
// Row softmax over g_scores, in place. One block per row (2048 elems, 256 thr)
// ---------------------------------------------------------------------------
__global__ __launch_bounds__(256) void softmax_rows() {
    size_t row = blockIdx.x;
    float* S = g_scores + row * TK;
    int tid = threadIdx.x;

    float4 v0 = ((const float4*)S)[tid];
    float4 v1 = ((const float4*)S)[tid + 256];

    float m = fmaxf(fmaxf(fmaxf(v0.x, v0.y), fmaxf(v0.z, v0.w)),
                    fmaxf(fmaxf(v1.x, v1.y), fmaxf(v1.z, v1.w)));

    __shared__ float red[8];
    // warp max
    #pragma unroll
    for (int o = 16; o; o >>= 1) m = fmaxf(m, __shfl_xor_sync(0xffffffffu, m, o));
    if ((tid & 31) == 0) red[tid >> 5] = m;
    __syncthreads();
    float rowmax = red[0];
    #pragma unroll
    for (int i = 1; i < 8; i++) rowmax = fmaxf(rowmax, red[i]);
    __syncthreads();

    v0.x = __expf(v0.x - rowmax); v0.y = __expf(v0.y - rowmax);
    v0.z = __expf(v0.z - rowmax); v0.w = __expf(v0.w - rowmax);
    v1.x = __expf(v1.x - rowmax); v1.y = __expf(v1.y - rowmax);
    v1.z = __expf(v1.z - rowmax); v1.w = __expf(v1.w - rowmax);

    float s = (v0.x + v0.y) + (v0.z + v0.w) + (v1.x + v1.y) + (v1.z + v1.w);
    #pragma unroll
    for (int o = 16; o; o >>= 1) s += __shfl_xor_sync(0xffffffffu, s, o);
    if ((tid & 31) == 0) red[tid >> 5] = s;
    __syncthreads();
    float rowsum = red[0];
    #pragma unroll
    for (int i = 1; i < 8; i++) rowsum += red[i];

    float inv = 1.0f / rowsum;
    v0.x *= inv; v0.y *= inv; v0.z *= inv; v0.w *= inv;
    v1.x *= inv; v1.y *= inv; v1.z *= inv; v1.w *= inv;

    ((float4*)S)[tid]       = v0;
    ((float4*)S)[tid + 256] = v1;
}

// ---------------------------------------------------------------------------
// GEMM 2 (NN): O[b] = P[b] @ V[b]
//   P: [TQ, TK] row-major (g_scores), V(enc): [TK, DD] row-major, O: [TQ, DD]
// ---------------------------------------------------------------------------
__global__ __launch_bounds__(256) void gemm_pv(const float* __restrict__ V,
                                               float* __restrict__ Out) {
    int b = blockIdx.z;
    const float* A  = g_scores + (size_t)b * TQ * TK;
    const float* Bm = V   + (size_t)b * TK * DD;
    float*       C  = Out + (size_t)b * TQ * DD;

    int bm = blockIdx.y * BM;
    int bn = blockIdx.x * BN;

    __shared__ float As[BK][BM];
    __shared__ float Bs[BK][BN];

    float acc[TM][TN] = {};
    int tid = threadIdx.x;
    int tx = tid & 15, ty = tid >> 4;

    for (int k0 = 0; k0 < TK; k0 += BK) {
        // A tile: 128 rows x 16 k (K-contiguous) -> transpose into As
        #pragma unroll
        for (int t = 0; t < 2; t++) {
            int j   = tid + t * 256;
            int row = j >> 2;
            int c4  = j & 3;
            float4 v = *(const float4*)&A[(size_t)(bm + row) * TK + k0 + c4 * 4];
            As[c4*4+0][row] = v.x; As[c4*4+1][row] = v.y;
            As[c4*4+2][row] = v.z; As[c4*4+3][row] = v.w;
            // B tile: 16 k-rows x 128 n (n-contiguous) -> direct store
            int r  = j >> 5;       // 0..15
            int n4 = j & 31;       // 0..31
            float4 w = *(const float4*)&Bm[(size_t)(k0 + r) * DD + bn + n4 * 4];
            *(float4*)&Bs[r][n4 * 4] = w;
        }
        __syncthreads();

        #pragma unroll
        for (int kk = 0; kk < BK; kk++) {
            float4 a0 = *(const float4*)&As[kk][ty * TM];
            float4 a1 = *(const float4*)&As[kk][ty * TM + 4];
            float4 b0 = *(const float4*)&Bs[kk][tx * TN];
            float4 b1 = *(const float4*)&Bs[kk][tx * TN + 4];
            float ar[8] = {a0.x,a0.y,a0.z,a0.w,a1.x,a1.y,a1.z,a1.w};
            float br[8] = {b0.x,b0.y,b0.z,b0.w,b1.x,b1.y,b1.z,b1.w};
            #pragma unroll
            for (int i = 0; i < 8; i++)
                #pragma unroll
                for (int j = 0; j < 8; j++)
                    acc[i][j] = fmaf(ar[i], br[j], acc[i][j]);
        }
        __syncthreads();
    }

    #pragma unroll
    for (int i = 0; i < 8; i++) {
        int m = bm + ty * TM + i;
        float4* crow = (float4*)&C[(size_t)m * DD + bn + tx * TN];
        crow[0] = make_float4(acc[i][0], acc[i][1], acc[i][2], acc[i][3]);
        crow[1] = make_float4(acc[i][4], acc[i][5], acc[i][6], acc[i][7]);
    }
}

// ---------------------------------------------------------------------------
extern "C" void kernel_launch(void* const* d_in, const int* in_sizes, int n_in,
                              void* d_out, int out_size) {
    const float* dec = (const float*)d_in[0];   // [32, 512, 512]
    const float* enc = (const float*)d_in[1];   // [32, 2048, 512]
    float* out = (float*)d_out;                 // [32, 512, 512]

    dim3 blk(256);
    gemm_qk<<<dim3(TK / BN, TQ / BM, B_), blk>>>(dec, enc);
    softmax_rows<<<B_ * TQ, blk>>>();
    gemm_pv<<<dim3(DD / BN, TQ / BM, B_), blk>>>(enc, out);
}

// round 6
// speedup vs baseline: 1.7188x; 1.7188x over previous
#include <cuda_runtime.h>
#include <cstdint>

#define B_  32
#define TQ  512
#define TK  2048
#define DD  512

// ---------------- static device scratch (no runtime allocation) -------------
__device__ float g_scores[(size_t)B_ * TQ * TK];  // scores, then tf32-rounded probs
__device__ float g_qhi[(size_t)B_ * TQ * DD];
__device__ float g_qlo[(size_t)B_ * TQ * DD];
__device__ float g_khi[(size_t)B_ * TK * DD];
__device__ float g_klo[(size_t)B_ * TK * DD];
__device__ float g_vt [(size_t)B_ * DD * TK];     // V^T tf32-rounded: [b][d][k]

// ---------------- helpers ----------------------------------------------------
__device__ __forceinline__ uint32_t smem_u32(const void* p) {
    uint32_t a;
    asm("{ .reg .u64 t; cvta.to.shared.u64 t, %1; cvt.u32.u64 %0, t; }" : "=r"(a) : "l"(p));
    return a;
}
__device__ __forceinline__ float tf32r(float x) {
    float y; asm("cvt.rna.tf32.f32 %0, %1;" : "=f"(y) : "f"(x)); return y;
}
__device__ __forceinline__ void ldsm4(uint32_t* r, uint32_t addr) {
    asm volatile("ldmatrix.sync.aligned.m8n8.x4.shared.b16 {%0,%1,%2,%3}, [%4];"
                 : "=r"(r[0]), "=r"(r[1]), "=r"(r[2]), "=r"(r[3]) : "r"(addr));
}
__device__ __forceinline__ void mma8(float* c, const uint32_t* a, uint32_t b0, uint32_t b1) {
    asm volatile("mma.sync.aligned.m16n8k8.row.col.f32.tf32.tf32.f32 "
                 "{%0,%1,%2,%3}, {%4,%5,%6,%7}, {%8,%9}, {%0,%1,%2,%3};"
                 : "+f"(c[0]), "+f"(c[1]), "+f"(c[2]), "+f"(c[3])
                 : "r"(a[0]), "r"(a[1]), "r"(a[2]), "r"(a[3]), "r"(b0), "r"(b1));
}
__device__ __forceinline__ void cpasync16(uint32_t dst, const void* src) {
    asm volatile("cp.async.cg.shared.global [%0], [%1], 16;" :: "r"(dst), "l"(src));
}
__device__ __forceinline__ void cp_commit() {
    asm volatile("cp.async.commit_group;" ::: "memory");
}
template <int N>
__device__ __forceinline__ void cp_wait() {
    asm volatile("cp.async.wait_group %0;" :: "n"(N) : "memory");
}

// XOR swizzle for 128B rows: bits[6:4] ^= bits[9:7]
#define SW(o) ((o) ^ (((o) >> 3) & 0x70u))

// ---------------- prep kernels ----------------------------------------------
__global__ __launch_bounds__(256) void split_tf32(const float* __restrict__ src,
                                                  float* __restrict__ hi,
                                                  float* __restrict__ lo, int n4) {
    int i = blockIdx.x * 256 + threadIdx.x;
    if (i >= n4) return;
    float4 v = ((const float4*)src)[i];
    float4 h, l;
    h.x = tf32r(v.x); l.x = tf32r(v.x - h.x);
    h.y = tf32r(v.y); l.y = tf32r(v.y - h.y);
    h.z = tf32r(v.z); l.z = tf32r(v.z - h.z);
    h.w = tf32r(v.w); l.w = tf32r(v.w - h.w);
    ((float4*)hi)[i] = h;
    ((float4*)lo)[i] = l;
}

// enc [b, 2048, 512] -> g_vt [b, 512, 2048], tf32-rounded
__global__ __launch_bounds__(256) void transpose_v(const float* __restrict__ enc,
                                                   float* __restrict__ vt) {
    __shared__ float tile[32][33];
    int b = blockIdx.z;
    int k0 = blockIdx.x * 32, d0 = blockIdx.y * 32;
    const float* E = enc + (size_t)b * TK * DD;
    float*       V = vt  + (size_t)b * DD * TK;
    #pragma unroll
    for (int i = threadIdx.y; i < 32; i += 8)
        tile[i][threadIdx.x] = E[(size_t)(k0 + i) * DD + d0 + threadIdx.x];
    __syncthreads();
    #pragma unroll
    for (int i = threadIdx.y; i < 32; i += 8)
        V[(size_t)(d0 + i) * TK + k0 + threadIdx.x] = tf32r(tile[threadIdx.x][i]);
}

// row softmax in place; probs rounded to tf32 so PV mma reads exact operands
__global__ __launch_bounds__(256) void softmax_rows() {
    size_t row = blockIdx.x;
    float* S = g_scores + row * TK;
    int tid = threadIdx.x;

    float4 v0 = ((const float4*)S)[tid];
    float4 v1 = ((const float4*)S)[tid + 256];

    float m = fmaxf(fmaxf(fmaxf(v0.x, v0.y), fmaxf(v0.z, v0.w)),
                    fmaxf(fmaxf(v1.x, v1.y), fmaxf(v1.z, v1.w)));
    __shared__ float red[8];
    #pragma unroll
    for (int o = 16; o; o >>= 1) m = fmaxf(m, __shfl_xor_sync(0xffffffffu, m, o));
    if ((tid & 31) == 0) red[tid >> 5] = m;
    __syncthreads();
    float rowmax = red[0];
    #pragma unroll
    for (int i = 1; i < 8; i++) rowmax = fmaxf(rowmax, red[i]);
    __syncthreads();

    v0.x = __expf(v0.x - rowmax); v0.y = __expf(v0.y - rowmax);
    v0.z = __expf(v0.z - rowmax); v0.w = __expf(v0.w - rowmax);
    v1.x = __expf(v1.x - rowmax); v1.y = __expf(v1.y - rowmax);
    v1.z = __expf(v1.z - rowmax); v1.w = __expf(v1.w - rowmax);

    float s = (v0.x + v0.y) + (v0.z + v0.w) + (v1.x + v1.y) + (v1.z + v1.w);
    #pragma unroll
    for (int o = 16; o; o >>= 1) s += __shfl_xor_sync(0xffffffffu, s, o);
    if ((tid & 31) == 0) red[tid >> 5] = s;
    __syncthreads();
    float rowsum = red[0];
    #pragma unroll
    for (int i = 1; i < 8; i++) rowsum += red[i];

    float inv = 1.0f / rowsum;
    v0.x = tf32r(v0.x * inv); v0.y = tf32r(v0.y * inv);
    v0.z = tf32r(v0.z * inv); v0.w = tf32r(v0.w * inv);
    v1.x = tf32r(v1.x * inv); v1.y = tf32r(v1.y * inv);
    v1.z = tf32r(v1.z * inv); v1.w = tf32r(v1.w * inv);

    ((float4*)S)[tid]       = v0;
    ((float4*)S)[tid + 256] = v1;
}

// ---------------- tf32 mma.sync GEMM ------------------------------------------
// C[128,128] per CTA: C[m,n] = sum_k A[m,k]*B[n,k]  (both operands K-major rows)
// NSPLIT=2: 3xTF32 (Ahi*Bhi + Ahi*Blo + Alo*Bhi); NSPLIT=1: plain tf32.
// 8 warps = 2(M) x 4(N); warp tile 64x32; m16n8k8 mma; cp.async multistage.
template <int NSPLIT, int KTILES, int STAGES>
__global__ __launch_bounds__(256, 1) void gemm_mma(
    const float* __restrict__ A0, const float* __restrict__ A1,
    const float* __restrict__ B0, const float* __restrict__ B1,
    float* __restrict__ C,
    int lda, int ldb, int ldc, size_t sA, size_t sB, size_t sC)
{
    constexpr int NTILES = 2 * NSPLIT;             // tiles per stage
    constexpr uint32_t TILE  = 128u * 128u;        // 16 KB (128 rows x 32 floats)
    constexpr uint32_t STAGE = NTILES * TILE;

    extern __shared__ char smem[];
    uint32_t sb = smem_u32(smem);

    int tid  = threadIdx.x;
    int lane = tid & 31, wid = tid >> 5;
    int wm = (wid >> 2) * 64;          // warp m offset (0 / 64)
    int wn = (wid & 3) * 32;           // warp n offset (0/32/64/96)
    int mbase = blockIdx.y * 128, nbase = blockIdx.x * 128, bz = blockIdx.z;

    // global tile sources, order: Ahi,(Alo),Bhi,(Blo)
    const float* gptr[NTILES];
    int gld[NTILES];
    gptr[0] = A0 + (size_t)bz * sA + (size_t)mbase * lda; gld[0] = lda;
    if (NSPLIT == 2) {
        gptr[1] = A1 + (size_t)bz * sA + (size_t)mbase * lda; gld[1] = lda;
        gptr[2] = B0 + (size_t)bz * sB + (size_t)nbase * ldb; gld[2] = ldb;
        gptr[3] = B1 + (size_t)bz * sB + (size_t)nbase * ldb; gld[3] = ldb;
    } else {
        gptr[1] = B0 + (size_t)bz * sB + (size_t)nbase * ldb; gld[1] = ldb;
    }

    auto load_stage = [&](int s, int kt) {
        uint32_t stbase = sb + (uint32_t)s * STAGE;
        int k0 = kt * 32;
        #pragma unroll
        for (int t = 0; t < NTILES; t++) {
            const char* g = (const char*)(gptr[t] + k0);
            uint32_t tb = stbase + t * TILE;
            #pragma unroll
            for (int i = 0; i < 4; i++) {
                int id  = tid + i * 256;
                int row = id >> 3, ch = id & 7;
                uint32_t off = row * 128 + ch * 16;
                cpasync16(tb + SW(off), g + (size_t)row * gld[t] * 4 + ch * 16);
            }
        }
    };

    // ldmatrix fragment addressing: row = base + (lane&15), col16 = (lane>>4)*16B
    uint32_t fraw = (uint32_t)((lane & 15) * 128 + ((lane >> 4) << 4));
    // XOR term depends only on (row % 8), invariant under +16-row / +32B-col steps
    uint32_t araw[4], brow[2];
    #pragma unroll
    for (int mt = 0; mt < 4; mt++) araw[mt] = (uint32_t)((wm + mt * 16) * 128) + fraw;
    #pragma unroll
    for (int np = 0; np < 2; np++) brow[np] = (uint32_t)((wn + np * 16) * 128) + fraw;

    float acc[4][4][4];
    #pragma unroll
    for (int i = 0; i < 4; i++)
        #pragma unroll
        for (int j = 0; j < 4; j++)
            #pragma unroll
            for (int k = 0; k < 4; k++) acc[i][j][k] = 0.0f;

    #pragma unroll
    for (int s = 0; s < STAGES - 1; s++) { load_stage(s, s); cp_commit(); }

    for (int kt = 0; kt < KTILES; kt++) {
        cp_wait<STAGES - 2>();
        __syncthreads();

        uint32_t stA  = sb + (uint32_t)(kt % STAGES) * STAGE;
        uint32_t stAl = stA + TILE;
        uint32_t stB  = stA + (NSPLIT == 2 ? 2 * TILE : TILE);
        uint32_t stBl = stB + TILE;

        #pragma unroll
        for (int kk = 0; kk < 4; kk++) {
            uint32_t kb = (uint32_t)(kk * 32);
            uint32_t ah[4][4], bh[2][4];
            uint32_t al[4][4], bl[2][4];
            #pragma unroll
            for (int mt = 0; mt < 4; mt++) {
                uint32_t o = araw[mt] + kb;
                ldsm4(ah[mt], stA + SW(o));
                if (NSPLIT == 2) ldsm4(al[mt], stAl + SW(o));
            }
            #pragma unroll
            for (int np = 0; np < 2; np++) {
                uint32_t o = brow[np] + kb;
                ldsm4(bh[np], stB + SW(o));
                if (NSPLIT == 2) ldsm4(bl[np], stBl + SW(o));
            }
            #pragma unroll
            for (int mt = 0; mt < 4; mt++)
                #pragma unroll
                for (int nt = 0; nt < 4; nt++) {
                    int np = nt >> 1, h = nt & 1;
                    mma8(acc[mt][nt], ah[mt], bh[np][h], bh[np][2 + h]);
                    if (NSPLIT == 2) {
                        mma8(acc[mt][nt], ah[mt], bl[np][h], bl[np][2 + h]);
                        mma8(acc[mt][nt], al[mt], bh[np][h], bh[np][2 + h]);
                    }
                }
        }
        __syncthreads();

        int nk = kt + STAGES - 1;
        if (nk < KTILES) load_stage(nk % STAGES, nk);
        cp_commit();
    }

    // epilogue
    float* c = C + (size_t)bz * sC;
    #pragma unroll
    for (int mt = 0; mt < 4; mt++)
        #pragma unroll
        for (int nt = 0; nt < 4; nt++) {
            int m = mbase + wm + mt * 16 + (lane >> 2);
            int n = nbase + wn + nt * 8 + (lane & 3) * 2;
            *(float2*)(c + (size_t)m * ldc + n) =
                make_float2(acc[mt][nt][0], acc[mt][nt][1]);
            *(float2*)(c + (size_t)(m + 8) * ldc + n) =
                make_float2(acc[mt][nt][2], acc[mt][nt][3]);
        }
}

// ---------------- host ---------------------------------------------------------
extern "C" void kernel_launch(void* const* d_in, const int* in_sizes, int n_in,
                              void* d_out, int out_size) {
    const float* dec = (const float*)d_in[0];   // [32, 512, 512]
    const float* enc = (const float*)d_in[1];   // [32, 2048, 512]
    float* out = (float*)d_out;                 // [32, 512, 512]

    void *p_sc, *p_qh, *p_ql, *p_kh, *p_kl, *p_vt;
    cudaGetSymbolAddress(&p_sc, g_scores);
    cudaGetSymbolAddress(&p_qh, g_qhi);
    cudaGetSymbolAddress(&p_ql, g_qlo);
    cudaGetSymbolAddress(&p_kh, g_khi);
    cudaGetSymbolAddress(&p_kl, g_klo);
    cudaGetSymbolAddress(&p_vt, g_vt);

    constexpr int SMEM_QK = 3 * 4 * 16384;   // 192 KB
    constexpr int SMEM_PV = 5 * 2 * 16384;   // 160 KB
    cudaFuncSetAttribute(gemm_mma<2, 16, 3>, cudaFuncAttributeMaxDynamicSharedMemorySize, SMEM_QK);
    cudaFuncSetAttribute(gemm_mma<1, 64, 5>, cudaFuncAttributeMaxDynamicSharedMemorySize, SMEM_PV);

    // prep
    split_tf32<<<(B_ * TQ * DD / 4 + 255) / 256, 256>>>(dec, (float*)p_qh, (float*)p_ql, B_ * TQ * DD / 4);
    split_tf32<<<(B_ * TK * DD / 4 + 255) / 256, 256>>>(enc, (float*)p_kh, (float*)p_kl, B_ * TK * DD / 4);
    transpose_v<<<dim3(TK / 32, DD / 32, B_), dim3(32, 8)>>>(enc, (float*)p_vt);

    // S = Q K^T (3xTF32)
    gemm_mma<2, 16, 3><<<dim3(TK / 128, TQ / 128, B_), 256, SMEM_QK>>>(
        (const float*)p_qh, (const float*)p_ql, (const float*)p_kh, (const float*)p_kl,
        (float*)p_sc, DD, DD, TK, (size_t)TQ * DD, (size_t)TK * DD, (size_t)TQ * TK);

    softmax_rows<<<B_ * TQ, 256>>>();

    // O = P V (plain tf32, pre-rounded operands)
    gemm_mma<1, 64, 5><<<dim3(DD / 128, TQ / 128, B_), 256, SMEM_PV>>>(
        (const float*)p_sc, nullptr, (const float*)p_vt, nullptr,
        out, TK, TK, DD, (size_t)TQ * TK, (size_t)DD * TK, (size_t)TQ * DD);
}